// round 11
// baseline (speedup 1.0000x reference)
#include <cuda_runtime.h>
#include <cuda_bf16.h>
#include <cstdint>

#define BB 128
#define SS 128
#define II 300
#define HH 1024
#define G4 4096
#define MTOT (BB*SS)          // 16384

// Scratch (static device arrays: allocation-free rule)
__device__ float g_Gin[(size_t)MTOT * G4];              // [S][B][4H] permuted gate pre-acts
__device__ __nv_bfloat16 g_hs_bf[(size_t)SS * BB * HH]; // [S][B][H] hidden states (bf16)
__device__ unsigned g_bar_count;
__device__ unsigned g_bar_gen;

__device__ __forceinline__ uint32_t f2b2(float lo, float hi){
    __nv_bfloat162 v = __floats2bfloat162_rn(lo, hi);
    return *(uint32_t*)&v;
}
__device__ __forceinline__ void mma_bf16(float* c, const uint32_t* a, uint32_t b0, uint32_t b1){
    asm volatile("mma.sync.aligned.m16n8k16.row.col.f32.bf16.bf16.f32 "
        "{%0,%1,%2,%3}, {%4,%5,%6,%7}, {%8,%9}, {%0,%1,%2,%3};\n"
        : "+f"(c[0]), "+f"(c[1]), "+f"(c[2]), "+f"(c[3])
        : "r"(a[0]), "r"(a[1]), "r"(a[2]), "r"(a[3]), "r"(b0), "r"(b1));
}
__device__ __forceinline__ void ldsm4(uint32_t* r, uint32_t addr){
    asm volatile("ldmatrix.sync.aligned.m8n8.x4.shared.b16 {%0,%1,%2,%3}, [%4];"
        : "=r"(r[0]), "=r"(r[1]), "=r"(r[2]), "=r"(r[3]) : "r"(addr));
}
__device__ __forceinline__ float sigmoidf_(float x){ return 1.f/(1.f + __expf(-x)); }
__device__ __forceinline__ float tanhf_(float x){
    float e = __expf(-2.f*fabsf(x));
    float t = (1.f - e)/(1.f + e);
    return x < 0.f ? -t : t;
}
// Gate-permuted column: n = g*1024 + u  ->  ct*32 + j_hi*16 + g_hi*8 + j_lo*2 + g_lo
__device__ __forceinline__ int permcol(int n){
    int g = n >> 10, u = n & 1023;
    int ct = u >> 3, j = u & 7;
    return ct*32 + ((j>>2)<<4) + ((g>>1)<<3) + ((j&3)<<1) + (g&1);
}

__device__ __forceinline__ void cp_async16(uint32_t s, const void* g){
    asm volatile("cp.async.ca.shared.global [%0], [%1], 16;\n" :: "r"(s), "l"(g) : "memory");
}
__device__ __forceinline__ void cp_commit(){ asm volatile("cp.async.commit_group;\n" ::: "memory"); }
__device__ __forceinline__ void cp_wait1(){ asm volatile("cp.async.wait_group 1;\n" ::: "memory"); }
__device__ __forceinline__ void cp_wait0(){ asm volatile("cp.async.wait_group 0;\n" ::: "memory"); }
__device__ __forceinline__ void bar_pair(int id){
    asm volatile("bar.sync %0, 64;" :: "r"(id) : "memory");
}

// ---------------------------------------------------------------------------
// Kernel 1: Gin[t][b][perm] = embed_W[x[b][t]] @ W_ih^T + (b_ih + b_hh)
// M=16384, N=4096, K=300 (10 k32 blocks, zero-padded). CTA 128x64, 8 warps.
// Double-buffered smem, ONE __syncthreads per k-iteration, register prefetch.
// ---------------------------------------------------------------------------
#define AST2 20               // smem row stride in words (80B): ldsm conflict-free
#define ABUF (128*AST2)       // words per A buffer
#define BBUF (64*AST2)        // words per B buffer
__global__ void __launch_bounds__(256) k_input_gemm(
    const int* __restrict__ x, const float* __restrict__ embW,
    const float* __restrict__ W_ih, const float* __restrict__ b_ih,
    const float* __restrict__ b_hh)
{
    __shared__ int      toks[128];
    __shared__ uint32_t As[2*ABUF];
    __shared__ uint32_t Bs[2*BBUF];
    const int tid = threadIdx.x, lane = tid & 31, warp = tid >> 5;
    const int gid = lane >> 2, tig = lane & 3;
    const int m0 = blockIdx.y * 128, n0 = blockIdx.x * 64;

    if (tid < 128){
        int m = m0 + tid;
        int t = m >> 7, b = m & 127;
        toks[tid] = x[b*SS + t];
    }
    __syncthreads();

    float acc[8][4];
    #pragma unroll
    for (int i=0;i<8;i++){ acc[i][0]=acc[i][1]=acc[i][2]=acc[i][3]=0.f; }

    // loaders: A thread -> row rowA, 16-col half; B thread -> row rowB, 8-col q
    const int rowA = tid >> 1, halfA = tid & 1;
    const int rowB = tid & 63, qB = tid >> 6;
    const size_t arow  = (size_t)toks[rowA]*II;
    const size_t browB = (size_t)(n0+rowB)*II;

    float4 va[4], vb[2];
    const float4 f4z = make_float4(0.f,0.f,0.f,0.f);
    {
        #pragma unroll
        for (int i=0;i<4;i++){
            int kg = halfA*16 + i*4;
            va[i] = (kg < II) ? *(const float4*)(embW + arow + kg) : f4z;
        }
        #pragma unroll
        for (int i=0;i<2;i++){
            int kg = qB*8 + i*4;
            vb[i] = (kg < II) ? *(const float4*)(W_ih + browB + kg) : f4z;
        }
    }

    // per-lane ldsm addresses (buffer 0 bases)
    uint32_t asb = (uint32_t)__cvta_generic_to_shared(As);
    uint32_t bsb = (uint32_t)__cvta_generic_to_shared(Bs);
    const int rowoff = (lane&7) + ((lane>>3)&1)*8;
    uint32_t aAddr = asb + (uint32_t)(((warp*16 + rowoff)*AST2 + ((lane>>4)&1)*4)*4);
    uint32_t bAddr[4];
    {
        int mi_ = lane >> 3;
        int ntl = mi_ >> 1, kh = mi_ & 1;
        #pragma unroll
        for (int p=0;p<4;p++)
            bAddr[p] = bsb + (uint32_t)((((p*2+ntl)*8 + (lane&7))*AST2 + kh*4)*4);
    }

    for (int kb = 0; kb < 10; kb++){
        const int sel = kb & 1;
        {   // store prefetched regs -> buf[sel]
            uint32_t* da = As + sel*ABUF + rowA*AST2 + halfA*8;
            uint4 w0 = make_uint4(f2b2(va[0].x,va[0].y), f2b2(va[0].z,va[0].w),
                                  f2b2(va[1].x,va[1].y), f2b2(va[1].z,va[1].w));
            uint4 w1 = make_uint4(f2b2(va[2].x,va[2].y), f2b2(va[2].z,va[2].w),
                                  f2b2(va[3].x,va[3].y), f2b2(va[3].z,va[3].w));
            *(uint4*)(da    ) = w0;
            *(uint4*)(da + 4) = w1;
            uint32_t* db = Bs + sel*BBUF + rowB*AST2 + qB*4;
            *(uint4*)db = make_uint4(f2b2(vb[0].x,vb[0].y), f2b2(vb[0].z,vb[0].w),
                                     f2b2(vb[1].x,vb[1].y), f2b2(vb[1].z,vb[1].w));
        }
        __syncthreads();

        if (kb < 9){   // prefetch next k-tile into regs
            int k0 = (kb+1)*32;
            #pragma unroll
            for (int i=0;i<4;i++){
                int kg = k0 + halfA*16 + i*4;
                va[i] = (kg < II) ? *(const float4*)(embW + arow + kg) : f4z;
            }
            #pragma unroll
            for (int i=0;i<2;i++){
                int kg = k0 + qB*8 + i*4;
                vb[i] = (kg < II) ? *(const float4*)(W_ih + browB + kg) : f4z;
            }
        }

        const uint32_t ao = (uint32_t)(sel*ABUF*4);
        const uint32_t bo = (uint32_t)(sel*BBUF*4);
        #pragma unroll
        for (int h=0; h<2; h++){           // two k16 halves of the k32 tile
            uint32_t a[4];
            ldsm4(a, aAddr + ao + h*32);
            #pragma unroll
            for (int p=0; p<4; p++){
                uint32_t b[4];
                ldsm4(b, bAddr[p] + bo + h*32);
                mma_bf16(acc[2*p  ], a, b[0], b[1]);
                mma_bf16(acc[2*p+1], a, b[2], b[3]);
            }
        }
        __syncthreads();
    }

    #pragma unroll
    for (int nt=0; nt<8; nt++){
        int n  = n0 + nt*8 + 2*tig;
        float bias0 = b_ih[n]   + b_hh[n];
        float bias1 = b_ih[n+1] + b_hh[n+1];
        int p0 = permcol(n), p1 = permcol(n+1);
        int mA = m0 + warp*16 + gid;
        float* r0 = g_Gin + (size_t)mA    *G4;
        float* r1 = g_Gin + (size_t)(mA+8)*G4;
        r0[p0] = acc[nt][0]+bias0; r0[p1] = acc[nt][1]+bias1;
        r1[p0] = acc[nt][2]+bias0; r1[p1] = acc[nt][3]+bias1;
    }
}

// ---------------------------------------------------------------------------
// Kernel 2: persistent LSTM recurrence, bf16 HMMA + ldmatrix, PAIR-LOCAL
// pipelines. 128 CTAs x 256 threads. Warps (mg, mg+4) form a pair sharing
// A-rows [32mg,32mg+32); each pair loads its own rows per chunk and syncs via
// a 64-thread named barrier (no CTA-wide sync inside the chunk loop).
// ---------------------------------------------------------------------------
#define CK    256
#define NCH   (HH/CK)            // 4
#define KPW   516                // Ws row stride (words); 516%32=4 -> LDSM conflict-free
#define HSW   132                // Hs row stride (words); 132%32=4
#define GSTR  36                 // Gin smem row stride (words)
#define WS_WORDS   (32*KPW)      // 16512
#define HB_WORDS   (128*HSW)     // 16896
#define GIN_WORDS  (128*GSTR)    // 4608
#define STG_WORDS  512
#define OFF_HB0  WS_WORDS
#define OFF_HB1  (WS_WORDS + HB_WORDS)
#define OFF_GIN  (WS_WORDS + 2*HB_WORDS)
#define OFF_STG  (OFF_GIN + GIN_WORDS)
#define SMEM_LSTM ((OFF_STG + STG_WORDS)*4)   // 221696 B

__device__ __forceinline__ void load_pair_chunk(uint32_t hb, const __nv_bfloat16* hsrc,
                                                int mg, int ptid){
    // rows [32mg, 32mg+32), 32 x 16B segs per row = 1024 segs / 64 pair-threads
    #pragma unroll
    for (int i=0;i<16;i++){
        int seg = i*64 + ptid;
        int rl = seg >> 5, s16 = seg & 31;
        int row = mg*32 + rl;
        cp_async16(hb + (uint32_t)(row*(HSW*4) + s16*16),
                   hsrc + (size_t)row*HH + s16*8);
    }
    cp_commit();
}

__global__ void __launch_bounds__(256) k_lstm(const float* __restrict__ W_hh)
{
    extern __shared__ uint32_t shm[];
    uint32_t* Ws   = shm;
    float*    GinF = (float*)(shm + OFF_GIN);
    __nv_bfloat16* Stage = (__nv_bfloat16*)(shm + OFF_STG);

    const int tid = threadIdx.x, lane = tid & 31, warp = tid >> 5;
    const int gid = lane >> 2, tig = lane & 3;
    const int mg = warp & 3, ng = warp >> 2;     // pair id / n-group
    const int ptid = ng*32 + lane;               // 0..63 within pair
    const int ct = blockIdx.x;
    const int u0 = ct * 8;
    const int j  = ng*4 + tig;                   // unit this lane owns

    const uint32_t sbase = (uint32_t)__cvta_generic_to_shared(shm);
    const uint32_t ginb  = sbase + OFF_GIN*4;
    const uint32_t hbb[2] = { sbase + OFF_HB0*4, sbase + OFF_HB1*4 };

    // Prefetch Gin tile for t=0 (overlaps weight load).
    {
        const float* gsrc = g_Gin + (size_t)ct*32;
        #pragma unroll
        for (int i=0;i<4;i++){
            int seg = i*256 + tid;
            int row = seg >> 3, s = seg & 7;
            cp_async16(ginb + (uint32_t)(row*(GSTR*4) + s*16),
                       gsrc + (size_t)row*G4 + s*4);
        }
        cp_commit();
    }

    // Load W_hh slice once, bf16-pair packed, rows in perm order.
    for (int idx = tid; idx < 32*512; idx += 256){
        int r = idx >> 9, kw = idx & 511;
        int jj_ = ((r>>4)<<2) + ((r>>1)&3);
        int gg_ = (((r>>3)&1)<<1) + (r&1);
        const float* src = W_hh + (size_t)(gg_*HH + u0 + jj_)*HH + 2*kw;
        Ws[r*KPW + kw] = f2b2(src[0], src[1]);
    }

    __shared__ unsigned sgen0;
    if (tid == 0) sgen0 = *(volatile unsigned*)&g_bar_gen;
    __syncthreads();
    const unsigned gen0 = sgen0;

    // per-lane ldmatrix addresses
    const int rowoff = (lane&7) + ((lane>>3)&1)*8;
    const int koffA  = ((lane>>4)&1)*4;
    const int mr = 32*mg;
    uint32_t aA[2];
    aA[0] = hbb[0] + (uint32_t)(((mr + rowoff)*HSW + koffA)*4);
    aA[1] = hbb[1] + (uint32_t)(((mr + rowoff)*HSW + koffA)*4);
    // B fragments: one ldsm4 covers both n-tiles (16 consecutive perm rows)
    uint32_t bA4;
    {
        int nt = (lane>>4)&1, kh = (lane>>3)&1;
        bA4 = sbase + (uint32_t)((((2*ng+nt)*8 + (lane&7))*KPW + kh*4)*4);
    }
    const int barid = 8 + mg;

    float cst[4];
    #pragma unroll
    for (int i=0;i<4;i++) cst[i] = 0.f;

    for (int t = 0; t < SS; t++){
        float acc[2][2][4];
        #pragma unroll
        for (int a1=0;a1<2;a1++)
            #pragma unroll
            for (int a2=0;a2<2;a2++)
                #pragma unroll
                for (int a3=0;a3<4;a3++) acc[a1][a2][a3] = 0.f;

        if (t > 0){
            const __nv_bfloat16* hprev = g_hs_bf + (size_t)(t-1)*BB*HH;

            load_pair_chunk(hbb[0], hprev,      mg, ptid);   // c0
            load_pair_chunk(hbb[1], hprev + CK, mg, ptid);   // c1

            #pragma unroll
            for (int c = 0; c < NCH; c++){
                if (c < 3) cp_wait1(); else cp_wait0();
                bar_pair(barid);                  // both halves of pair data visible

                const uint32_t aBase = aA[c&1];
                const uint32_t bOff  = (uint32_t)(c*512);
                #pragma unroll
                for (int s = 0; s < CK/16; s++){
                    uint32_t a0[4], a1v[4], b4[4];
                    ldsm4(a0,  aBase + s*32);
                    ldsm4(a1v, aBase + s*32 + 16*HSW*4);
                    ldsm4(b4,  bA4 + bOff + s*32);
                    mma_bf16(acc[0][0], a0,  b4[0], b4[1]);
                    mma_bf16(acc[0][1], a0,  b4[2], b4[3]);
                    mma_bf16(acc[1][0], a1v, b4[0], b4[1]);
                    mma_bf16(acc[1][1], a1v, b4[2], b4[3]);
                }

                if (c < 2){
                    bar_pair(barid);              // pair done reading buf[c&1]
                    load_pair_chunk(hbb[c&1], hprev + (c+2)*CK, mg, ptid);
                }
            }
            __syncthreads();                      // Gin writes visible to all
        } else {
            cp_wait0();
            __syncthreads();
        }

        // Epilogue: lane owns unit j for 4 m-rows; Gin read from smem.
        #pragma unroll
        for (int mi=0; mi<4; mi++){
            int mt = mi >> 1, hi = mi & 1;
            int m  = mr + 16*mt + gid + 8*hi;
            const float* gp = GinF + m*GSTR + ng*16 + 2*tig;
            float2 fif = *(const float2*)(gp    );
            float2 fgo = *(const float2*)(gp + 8);
            float iv = acc[mt][0][2*hi+0] + fif.x;
            float fv = acc[mt][0][2*hi+1] + fif.y;
            float gv = acc[mt][1][2*hi+0] + fgo.x;
            float ov = acc[mt][1][2*hi+1] + fgo.y;
            float cv = sigmoidf_(fv)*cst[mi] + sigmoidf_(iv)*tanhf_(gv);
            cst[mi] = cv;
            float hv = sigmoidf_(ov)*tanhf_(cv);
            Stage[m*8 + j] = __float2bfloat16(hv);
        }
        __syncthreads();                          // stage complete; Gin reads done

        if (tid < 128){
            uint4 v = *(const uint4*)(Stage + tid*8);
            *(uint4*)(g_hs_bf + (size_t)t*BB*HH + (size_t)tid*HH + u0) = v;
        }

        if (t < SS-1){
            // Prefetch Gin for t+1 before the grid barrier.
            const float* gsrc = g_Gin + (size_t)(t+1)*BB*G4 + ct*32;
            #pragma unroll
            for (int i=0;i<4;i++){
                int seg = i*256 + tid;
                int row = seg >> 3, s = seg & 7;
                cp_async16(ginb + (uint32_t)(row*(GSTR*4) + s*16),
                           gsrc + (size_t)row*G4 + s*4);
            }
            cp_commit();

            __threadfence();                      // release h writes
            __syncthreads();
            if (tid == 0){
                unsigned prev = atomicAdd(&g_bar_count, 1u);
                if (prev == gridDim.x - 1){
                    atomicExch(&g_bar_count, 0u);
                    __threadfence();
                    atomicAdd(&g_bar_gen, 1u);
                } else {
                    unsigned target = gen0 + (unsigned)(t+1);
                    while ((int)(*(volatile unsigned*)&g_bar_gen - target) < 0) {}
                }
                __threadfence();
            }
            __syncthreads();
        }
    }
}

// ---------------------------------------------------------------------------
// Kernel 3: out[b*S+t][:] = valid ? hs[t][b] @ lin_W^T + lin_b : (1, 0)
// One warp per output row; vectorized uint4 h loads.
// ---------------------------------------------------------------------------
__global__ void __launch_bounds__(256) k_output(
    const int* __restrict__ lengths, const float* __restrict__ lin_W,
    const float* __restrict__ lin_b, float* __restrict__ out)
{
    int row = blockIdx.x * 8 + (threadIdx.x >> 5);
    if (row >= MTOT) return;
    int lane = threadIdx.x & 31;
    int b = row >> 7, t = row & 127;
    float2 res;
    if (t < lengths[b]){
        const uint4* h4 = (const uint4*)(g_hs_bf + ((size_t)t*BB + b)*HH);
        float s0 = 0.f, s1 = 0.f;
        #pragma unroll
        for (int k4 = lane; k4 < 128; k4 += 32){    // 8 bf16 per uint4
            uint4 hv = h4[k4];
            const __nv_bfloat162* hp = (const __nv_bfloat162*)&hv;
            int kb = k4*8;
            const float4* w0 = (const float4*)(lin_W + kb);
            const float4* w1 = (const float4*)(lin_W + HH + kb);
            #pragma unroll
            for (int q=0;q<4;q++){
                float2 hf = __bfloat1622float2(hp[q]);
                float2 wa = q<2 ? (q==0 ? make_float2(w0[0].x,w0[0].y)
                                        : make_float2(w0[0].z,w0[0].w))
                               : (q==2 ? make_float2(w0[1].x,w0[1].y)
                                        : make_float2(w0[1].z,w0[1].w));
                float2 wb = q<2 ? (q==0 ? make_float2(w1[0].x,w1[0].y)
                                        : make_float2(w1[0].z,w1[0].w))
                               : (q==2 ? make_float2(w1[1].x,w1[1].y)
                                        : make_float2(w1[1].z,w1[1].w));
                s0 += hf.x*wa.x + hf.y*wa.y;
                s1 += hf.x*wb.x + hf.y*wb.y;
            }
        }
        #pragma unroll
        for (int off = 16; off > 0; off >>= 1){
            s0 += __shfl_down_sync(0xffffffffu, s0, off);
            s1 += __shfl_down_sync(0xffffffffu, s1, off);
        }
        res = make_float2(s0 + lin_b[0], s1 + lin_b[1]);
    } else {
        res = make_float2(1.f, 0.f);
    }
    if (lane == 0) *(float2*)(out + (size_t)row*2) = res;
}

// ---------------------------------------------------------------------------
extern "C" void kernel_launch(void* const* d_in, const int* in_sizes, int n_in,
                              void* d_out, int out_size)
{
    const int*   x       = (const int*)  d_in[0];
    const int*   lengths = (const int*)  d_in[1];
    const float* embW    = (const float*)d_in[2];
    const float* W_ih    = (const float*)d_in[3];
    const float* W_hh    = (const float*)d_in[4];
    const float* b_ih    = (const float*)d_in[5];
    const float* b_hh    = (const float*)d_in[6];
    const float* lin_W   = (const float*)d_in[7];
    const float* lin_b   = (const float*)d_in[8];
    float* out = (float*)d_out;

    cudaFuncSetAttribute(k_lstm, cudaFuncAttributeMaxDynamicSharedMemorySize, SMEM_LSTM);

    dim3 gA(G4/64, MTOT/128);   // 64 x 128 CTAs
    k_input_gemm<<<gA, 256>>>(x, embW, W_ih, b_ih, b_hh);
    k_lstm<<<128, 256, SMEM_LSTM>>>(W_hh);
    k_output<<<(MTOT+7)/8, 256>>>(lengths, lin_W, lin_b, out);
}